// round 1
// baseline (speedup 1.0000x reference)
#include <cuda_runtime.h>
#include <math.h>

#define N    2048
#define HID  16
#define TPB  256
#define JPT  (N / TPB)   // 8 j's per thread

// Per-signal derived scalars (SoA): t, ra, dec, chirp_mass, f_isco, dist, psi
__device__ float g_pre[7 * N];

__global__ void pre_kernel(const float* __restrict__ p) {
    int i = blockIdx.x * blockDim.x + threadIdx.x;
    if (i >= N) return;
    const float* pi = p + i * 15;
    float m1 = fmaf(pi[0], 95.f, 5.f);
    float m2 = fmaf(pi[1], 95.f, 5.f);
    float mc = powf(m1 * m2, 0.6f) / powf(m1 + m2, 0.2f);
    g_pre[0 * N + i] = pi[5];                    // t
    g_pre[1 * N + i] = pi[3];                    // ra
    g_pre[2 * N + i] = pi[4];                    // dec
    g_pre[3 * N + i] = mc;                       // chirp mass
    g_pre[4 * N + i] = 220.f / (m1 + m2);        // f_isco
    g_pre[5 * N + i] = fmaf(pi[2], 2950.f, 50.f);// dist
    g_pre[6 * N + i] = pi[7];                    // psi
}

__device__ __forceinline__ float gelu_erf(float x) {
    return 0.5f * x * (1.f + erff(x * 0.70710678118654752f));
}

__global__ __launch_bounds__(TPB) void row_kernel(
    const float* __restrict__ iw1, const float* __restrict__ ib1,
    const float* __restrict__ ig1, const float* __restrict__ ibt1,
    const float* __restrict__ iw2, const float* __restrict__ ib2,
    const float* __restrict__ ow1, const float* __restrict__ ob1,
    const float* __restrict__ og1, const float* __restrict__ obt1,
    const float* __restrict__ ow2, const float* __restrict__ ob2,
    float* __restrict__ out)
{
    __shared__ float s_logits[N];       // logits, then exp values
    __shared__ float s_w1[HID * 8];     // importance-net layer-1 weights
    __shared__ float s_red[8];          // per-warp reduction scratch
    __shared__ float s_red8[8][8];      // per-warp x per-feature scratch
    __shared__ float s_bcast[2];        // max, sum
    __shared__ float s_wsum[8];         // weighted feature vector
    __shared__ float s_h2[32];          // overlap-net hidden

    const int tid  = threadIdx.x;
    const int i    = blockIdx.x;
    const int lane = tid & 31;
    const int wid  = tid >> 5;

    if (tid < HID * 8) s_w1[tid] = iw1[tid];

    // Small weight vectors live in registers (uniform broadcast loads)
    float b1v[HID], g1v[HID], bt1v[HID], w2v[HID];
#pragma unroll
    for (int h = 0; h < HID; h++) {
        b1v[h]  = ib1[h];
        g1v[h]  = ig1[h];
        bt1v[h] = ibt1[h];
        w2v[h]  = iw2[h];
    }
    const float b2 = ib2[0];

    const float* pt  = g_pre;
    const float* pra = g_pre + N;
    const float* pde = g_pre + 2 * N;
    const float* pmc = g_pre + 3 * N;
    const float* pfi = g_pre + 4 * N;
    const float* pdi = g_pre + 5 * N;
    const float* pps = g_pre + 6 * N;

    const float ti  = pt[i],  rai = pra[i], dei = pde[i], mci = pmc[i];
    const float fii = pfi[i], dii = pdi[i], psi = pps[i];

    __syncthreads();

    // ---------- Pass 1: importance-net logits for row i ----------
    float lmax = -INFINITY;
#pragma unroll
    for (int jj = 0; jj < JPT; jj++) {
        const int j = (jj << 8) | tid;
        float logit;
        if (j == i) {
            logit = -INFINITY;
        } else {
            float dra = fabsf(rai - pra[j]);
            float dde = fabsf(dei - pde[j]);
            float f0 = fabsf(ti - pt[j]);
            float f1 = sqrtf(fmaf(dra, dra, dde * dde));
            float f2 = __fdividef(1.f, fmaf(fabsf(mci - pmc[j]), (1.f / 30.f), 1.f));
            float f3 = __expf(-fabsf(fii - pfi[j]) * 0.01f);
            float dj = pdi[j];
            float f4 = __fdividef(fminf(dii, dj), fmaxf(dii, dj));
            float f5 = fabsf(psi - pps[j]);
            float f6 = dra, f7 = dde;

            float z[HID];
            float mean = 0.f;
#pragma unroll
            for (int h = 0; h < HID; h++) {
                const float* w = s_w1 + h * 8;
                float a = b1v[h];
                a = fmaf(w[0], f0, a); a = fmaf(w[1], f1, a);
                a = fmaf(w[2], f2, a); a = fmaf(w[3], f3, a);
                a = fmaf(w[4], f4, a); a = fmaf(w[5], f5, a);
                a = fmaf(w[6], f6, a); a = fmaf(w[7], f7, a);
                z[h] = a;
                mean += a;
            }
            mean *= (1.f / HID);
            float var = 0.f;
#pragma unroll
            for (int h = 0; h < HID; h++) {
                float d = z[h] - mean;
                var = fmaf(d, d, var);
            }
            float inv = rsqrtf(fmaf(var, (1.f / HID), 1e-5f));
            float lg = b2;
#pragma unroll
            for (int h = 0; h < HID; h++) {
                float xn = fmaf((z[h] - mean) * inv, g1v[h], bt1v[h]);
                lg = fmaf(w2v[h], gelu_erf(xn), lg);
            }
            logit = lg;
        }
        s_logits[j] = logit;
        lmax = fmaxf(lmax, logit);
    }

    // ---------- Block max ----------
#pragma unroll
    for (int o = 16; o; o >>= 1) lmax = fmaxf(lmax, __shfl_xor_sync(0xFFFFFFFFu, lmax, o));
    if (lane == 0) s_red[wid] = lmax;
    __syncthreads();
    if (wid == 0) {
        float m = s_red[lane & 7];
#pragma unroll
        for (int o = 4; o; o >>= 1) m = fmaxf(m, __shfl_xor_sync(0xFFFFFFFFu, m, o));
        if (lane == 0) s_bcast[0] = m;
    }
    __syncthreads();
    const float m = s_bcast[0];

    // ---------- Exp + block sum (exp(-inf) = 0 handles the diagonal) ----------
    float lsum = 0.f;
#pragma unroll
    for (int jj = 0; jj < JPT; jj++) {
        const int j = (jj << 8) | tid;
        float e = __expf(s_logits[j] - m);
        s_logits[j] = e;
        lsum += e;
    }
#pragma unroll
    for (int o = 16; o; o >>= 1) lsum += __shfl_xor_sync(0xFFFFFFFFu, lsum, o);
    if (lane == 0) s_red[wid] = lsum;
    __syncthreads();
    if (wid == 0) {
        float s = s_red[lane & 7];
#pragma unroll
        for (int o = 4; o; o >>= 1) s += __shfl_xor_sync(0xFFFFFFFFu, s, o);
        if (lane == 0) s_bcast[1] = s;
    }
    __syncthreads();
    const float invsum = 1.f / s_bcast[1];

    // ---------- Pass 2: attention-weighted features (cheap recompute) ----------
    float acc0 = 0, acc1 = 0, acc2 = 0, acc3 = 0, acc4 = 0, acc5 = 0, acc6 = 0, acc7 = 0;
#pragma unroll
    for (int jj = 0; jj < JPT; jj++) {
        const int j = (jj << 8) | tid;
        float w = s_logits[j] * invsum;   // 0 at j == i
        float dra = fabsf(rai - pra[j]);
        float dde = fabsf(dei - pde[j]);
        float dj  = pdi[j];
        acc0 = fmaf(w, fabsf(ti - pt[j]), acc0);
        acc1 = fmaf(w, sqrtf(fmaf(dra, dra, dde * dde)), acc1);
        acc2 = fmaf(w, __fdividef(1.f, fmaf(fabsf(mci - pmc[j]), (1.f / 30.f), 1.f)), acc2);
        acc3 = fmaf(w, __expf(-fabsf(fii - pfi[j]) * 0.01f), acc3);
        acc4 = fmaf(w, __fdividef(fminf(dii, dj), fmaxf(dii, dj)), acc4);
        acc5 = fmaf(w, fabsf(psi - pps[j]), acc5);
        acc6 = fmaf(w, dra, acc6);
        acc7 = fmaf(w, dde, acc7);
    }
    float accs[8] = {acc0, acc1, acc2, acc3, acc4, acc5, acc6, acc7};
#pragma unroll
    for (int f = 0; f < 8; f++) {
        float v = accs[f];
#pragma unroll
        for (int o = 16; o; o >>= 1) v += __shfl_xor_sync(0xFFFFFFFFu, v, o);
        if (lane == 0) s_red8[wid][f] = v;
    }
    __syncthreads();
    if (tid < 8) {
        float v = 0.f;
#pragma unroll
        for (int w = 0; w < 8; w++) v += s_red8[w][tid];
        s_wsum[tid] = v;
    }
    __syncthreads();

    // ---------- Overlap net: 8 -> 32 (LN + gelu) -> 16, warp 0 only ----------
    if (tid < 32) {
        float a = ob1[tid];
#pragma unroll
        for (int f = 0; f < 8; f++) a = fmaf(ow1[tid * 8 + f], s_wsum[f], a);
        float s = a;
#pragma unroll
        for (int o = 16; o; o >>= 1) s += __shfl_xor_sync(0xFFFFFFFFu, s, o);
        float mu = s * (1.f / 32.f);
        float d = a - mu;
        float v = d * d;
#pragma unroll
        for (int o = 16; o; o >>= 1) v += __shfl_xor_sync(0xFFFFFFFFu, v, o);
        float invs = rsqrtf(fmaf(v, (1.f / 32.f), 1e-5f));
        float xn = fmaf(d * invs, og1[tid], obt1[tid]);
        s_h2[tid] = gelu_erf(xn);
        __syncwarp();
        if (tid < 16) {
            float o_ = ob2[tid];
#pragma unroll
            for (int k = 0; k < 32; k++) o_ = fmaf(ow2[tid * 32 + k], s_h2[k], o_);
            out[i * 16 + tid] = o_;
        }
    }
}

extern "C" void kernel_launch(void* const* d_in, const int* in_sizes, int n_in,
                              void* d_out, int out_size) {
    const float* params = (const float*)d_in[0];
    const float* iw1  = (const float*)d_in[1];
    const float* ib1  = (const float*)d_in[2];
    const float* ig1  = (const float*)d_in[3];
    const float* ibt1 = (const float*)d_in[4];
    const float* iw2  = (const float*)d_in[5];
    const float* ib2  = (const float*)d_in[6];
    const float* ow1  = (const float*)d_in[7];
    const float* ob1  = (const float*)d_in[8];
    const float* og1  = (const float*)d_in[9];
    const float* obt1 = (const float*)d_in[10];
    const float* ow2  = (const float*)d_in[11];
    const float* ob2  = (const float*)d_in[12];
    float* out = (float*)d_out;

    pre_kernel<<<(N + 255) / 256, 256>>>(params);
    row_kernel<<<N, TPB>>>(iw1, ib1, ig1, ibt1, iw2, ib2,
                           ow1, ob1, og1, obt1, ow2, ob2, out);
}

// round 2
// speedup vs baseline: 1.2694x; 1.2694x over previous
#include <cuda_runtime.h>
#include <math.h>

#define N    2048
#define HID  16
#define TPB  256

// Per-signal derived scalars (SoA): t, ra, dec, chirp_mass, f_isco, dist, psi
__device__ float g_pre[7 * N];
// Full logits matrix (16 MB, L2-resident). Symmetric; diagonal = -inf.
__device__ float g_logits[N * N];

__global__ void pre_kernel(const float* __restrict__ p) {
    int i = blockIdx.x * blockDim.x + threadIdx.x;
    if (i >= N) return;
    const float* pi = p + i * 15;
    float m1 = fmaf(pi[0], 95.f, 5.f);
    float m2 = fmaf(pi[1], 95.f, 5.f);
    float mc = powf(m1 * m2, 0.6f) / powf(m1 + m2, 0.2f);
    g_pre[0 * N + i] = pi[5];                    // t
    g_pre[1 * N + i] = pi[3];                    // ra
    g_pre[2 * N + i] = pi[4];                    // dec
    g_pre[3 * N + i] = mc;                       // chirp mass
    g_pre[4 * N + i] = 220.f / (m1 + m2);        // f_isco
    g_pre[5 * N + i] = fmaf(pi[2], 2950.f, 50.f);// dist
    g_pre[6 * N + i] = pi[7];                    // psi
}

__device__ __forceinline__ float gelu_erf(float x) {
    return 0.5f * x * (1.f + erff(x * 0.70710678118654752f));
}

// ---------------------------------------------------------------------------
// Kernel B: importance-net logits, upper triangle only (j > i), mirrored.
// ---------------------------------------------------------------------------
__global__ __launch_bounds__(TPB) void logits_kernel(
    const float* __restrict__ iw1, const float* __restrict__ ib1,
    const float* __restrict__ ig1, const float* __restrict__ ibt1,
    const float* __restrict__ iw2, const float* __restrict__ ib2)
{
    __shared__ float s_w1[HID * 8];

    const int tid = threadIdx.x;
    const int i   = blockIdx.x;

    if (tid < HID * 8) s_w1[tid] = iw1[tid];

    float b1v[HID], g1v[HID], bt1v[HID], w2v[HID];
#pragma unroll
    for (int h = 0; h < HID; h++) {
        b1v[h]  = ib1[h];
        g1v[h]  = ig1[h];
        bt1v[h] = ibt1[h];
        w2v[h]  = iw2[h];
    }
    const float b2 = ib2[0];

    const float* pt  = g_pre;
    const float* pra = g_pre + N;
    const float* pde = g_pre + 2 * N;
    const float* pmc = g_pre + 3 * N;
    const float* pfi = g_pre + 4 * N;
    const float* pdi = g_pre + 5 * N;
    const float* pps = g_pre + 6 * N;

    const float ti  = pt[i],  rai = pra[i], dei = pde[i], mci = pmc[i];
    const float fii = pfi[i], dii = pdi[i], psi = pps[i];

    if (tid == 0) g_logits[i * N + i] = -INFINITY;

    __syncthreads();

    for (int j = i + 1 + tid; j < N; j += TPB) {
        float dra = fabsf(rai - pra[j]);
        float dde = fabsf(dei - pde[j]);
        float f0 = fabsf(ti - pt[j]);
        float f1 = sqrtf(fmaf(dra, dra, dde * dde));
        float f2 = __fdividef(1.f, fmaf(fabsf(mci - pmc[j]), (1.f / 30.f), 1.f));
        float f3 = __expf(-fabsf(fii - pfi[j]) * 0.01f);
        float dj = pdi[j];
        float f4 = __fdividef(fminf(dii, dj), fmaxf(dii, dj));
        float f5 = fabsf(psi - pps[j]);
        float f6 = dra, f7 = dde;

        float z[HID];
        float mean = 0.f;
#pragma unroll
        for (int h = 0; h < HID; h++) {
            const float* w = s_w1 + h * 8;
            float a = b1v[h];
            a = fmaf(w[0], f0, a); a = fmaf(w[1], f1, a);
            a = fmaf(w[2], f2, a); a = fmaf(w[3], f3, a);
            a = fmaf(w[4], f4, a); a = fmaf(w[5], f5, a);
            a = fmaf(w[6], f6, a); a = fmaf(w[7], f7, a);
            z[h] = a;
            mean += a;
        }
        mean *= (1.f / HID);
        float var = 0.f;
#pragma unroll
        for (int h = 0; h < HID; h++) {
            float d = z[h] - mean;
            var = fmaf(d, d, var);
        }
        float inv = rsqrtf(fmaf(var, (1.f / HID), 1e-5f));
        float lg = b2;
#pragma unroll
        for (int h = 0; h < HID; h++) {
            float xn = fmaf((z[h] - mean) * inv, g1v[h], bt1v[h]);
            lg = fmaf(w2v[h], gelu_erf(xn), lg);
        }
        g_logits[i * N + j] = lg;   // coalesced
        g_logits[j * N + i] = lg;   // mirrored (uncoalesced, L2-absorbed)
    }
}

// ---------------------------------------------------------------------------
// Kernel C: per-row softmax + weighted features + overlap net.
// ---------------------------------------------------------------------------
__global__ __launch_bounds__(TPB) void row2_kernel(
    const float* __restrict__ ow1, const float* __restrict__ ob1,
    const float* __restrict__ og1, const float* __restrict__ obt1,
    const float* __restrict__ ow2, const float* __restrict__ ob2,
    float* __restrict__ out)
{
    __shared__ float s_red[8];
    __shared__ float s_red8[8][8];
    __shared__ float s_bcast[2];
    __shared__ float s_wsum[8];
    __shared__ float s_h2[32];

    const int tid  = threadIdx.x;
    const int i    = blockIdx.x;
    const int lane = tid & 31;
    const int wid  = tid >> 5;

    const float* pt  = g_pre;
    const float* pra = g_pre + N;
    const float* pde = g_pre + 2 * N;
    const float* pmc = g_pre + 3 * N;
    const float* pfi = g_pre + 4 * N;
    const float* pdi = g_pre + 5 * N;
    const float* pps = g_pre + 6 * N;

    const float ti  = pt[i],  rai = pra[i], dei = pde[i], mci = pmc[i];
    const float fii = pfi[i], dii = pdi[i], psi = pps[i];

    // ---- load row of logits into registers, find max ----
    float lg[8];
    float lmax = -INFINITY;
    const float* rowp = g_logits + (size_t)i * N;
#pragma unroll
    for (int jj = 0; jj < 8; jj++) {
        lg[jj] = rowp[(jj << 8) | tid];
        lmax = fmaxf(lmax, lg[jj]);
    }
#pragma unroll
    for (int o = 16; o; o >>= 1) lmax = fmaxf(lmax, __shfl_xor_sync(0xFFFFFFFFu, lmax, o));
    if (lane == 0) s_red[wid] = lmax;
    __syncthreads();
    if (wid == 0) {
        float m = s_red[lane & 7];
#pragma unroll
        for (int o = 4; o; o >>= 1) m = fmaxf(m, __shfl_xor_sync(0xFFFFFFFFu, m, o));
        if (lane == 0) s_bcast[0] = m;
    }
    __syncthreads();
    const float m = s_bcast[0];

    // ---- exp + sum (exp(-inf)=0 handles diagonal) ----
    float lsum = 0.f;
#pragma unroll
    for (int jj = 0; jj < 8; jj++) {
        lg[jj] = __expf(lg[jj] - m);
        lsum += lg[jj];
    }
#pragma unroll
    for (int o = 16; o; o >>= 1) lsum += __shfl_xor_sync(0xFFFFFFFFu, lsum, o);
    if (lane == 0) s_red[wid] = lsum;
    __syncthreads();
    if (wid == 0) {
        float s = s_red[lane & 7];
#pragma unroll
        for (int o = 4; o; o >>= 1) s += __shfl_xor_sync(0xFFFFFFFFu, s, o);
        if (lane == 0) s_bcast[1] = s;
    }
    __syncthreads();
    const float invsum = 1.f / s_bcast[1];

    // ---- attention-weighted features (cheap recompute) ----
    float acc0 = 0, acc1 = 0, acc2 = 0, acc3 = 0, acc4 = 0, acc5 = 0, acc6 = 0, acc7 = 0;
#pragma unroll
    for (int jj = 0; jj < 8; jj++) {
        const int j = (jj << 8) | tid;
        float w = lg[jj] * invsum;
        float dra = fabsf(rai - pra[j]);
        float dde = fabsf(dei - pde[j]);
        float dj  = pdi[j];
        acc0 = fmaf(w, fabsf(ti - pt[j]), acc0);
        acc1 = fmaf(w, sqrtf(fmaf(dra, dra, dde * dde)), acc1);
        acc2 = fmaf(w, __fdividef(1.f, fmaf(fabsf(mci - pmc[j]), (1.f / 30.f), 1.f)), acc2);
        acc3 = fmaf(w, __expf(-fabsf(fii - pfi[j]) * 0.01f), acc3);
        acc4 = fmaf(w, __fdividef(fminf(dii, dj), fmaxf(dii, dj)), acc4);
        acc5 = fmaf(w, fabsf(psi - pps[j]), acc5);
        acc6 = fmaf(w, dra, acc6);
        acc7 = fmaf(w, dde, acc7);
    }
    float accs[8] = {acc0, acc1, acc2, acc3, acc4, acc5, acc6, acc7};
#pragma unroll
    for (int f = 0; f < 8; f++) {
        float v = accs[f];
#pragma unroll
        for (int o = 16; o; o >>= 1) v += __shfl_xor_sync(0xFFFFFFFFu, v, o);
        if (lane == 0) s_red8[wid][f] = v;
    }
    __syncthreads();
    if (tid < 8) {
        float v = 0.f;
#pragma unroll
        for (int w = 0; w < 8; w++) v += s_red8[w][tid];
        s_wsum[tid] = v;
    }
    __syncthreads();

    // ---- overlap net: 8 -> 32 (LN + gelu) -> 16, warp 0 only ----
    if (tid < 32) {
        float a = ob1[tid];
#pragma unroll
        for (int f = 0; f < 8; f++) a = fmaf(ow1[tid * 8 + f], s_wsum[f], a);
        float s = a;
#pragma unroll
        for (int o = 16; o; o >>= 1) s += __shfl_xor_sync(0xFFFFFFFFu, s, o);
        float mu = s * (1.f / 32.f);
        float d = a - mu;
        float v = d * d;
#pragma unroll
        for (int o = 16; o; o >>= 1) v += __shfl_xor_sync(0xFFFFFFFFu, v, o);
        float invs = rsqrtf(fmaf(v, (1.f / 32.f), 1e-5f));
        float xn = fmaf(d * invs, og1[tid], obt1[tid]);
        s_h2[tid] = gelu_erf(xn);
        __syncwarp();
        if (tid < 16) {
            float o_ = ob2[tid];
#pragma unroll
            for (int k = 0; k < 32; k++) o_ = fmaf(ow2[tid * 32 + k], s_h2[k], o_);
            out[i * 16 + tid] = o_;
        }
    }
}

extern "C" void kernel_launch(void* const* d_in, const int* in_sizes, int n_in,
                              void* d_out, int out_size) {
    const float* params = (const float*)d_in[0];
    const float* iw1  = (const float*)d_in[1];
    const float* ib1  = (const float*)d_in[2];
    const float* ig1  = (const float*)d_in[3];
    const float* ibt1 = (const float*)d_in[4];
    const float* iw2  = (const float*)d_in[5];
    const float* ib2  = (const float*)d_in[6];
    const float* ow1  = (const float*)d_in[7];
    const float* ob1  = (const float*)d_in[8];
    const float* og1  = (const float*)d_in[9];
    const float* obt1 = (const float*)d_in[10];
    const float* ow2  = (const float*)d_in[11];
    const float* ob2  = (const float*)d_in[12];
    float* out = (float*)d_out;

    pre_kernel<<<(N + 255) / 256, 256>>>(params);
    logits_kernel<<<N, TPB>>>(iw1, ib1, ig1, ibt1, iw2, ib2);
    row2_kernel<<<N, TPB>>>(ow1, ob1, og1, obt1, ow2, ob2, out);
}